// round 5
// baseline (speedup 1.0000x reference)
#include <cuda_runtime.h>
#include <cuda_bf16.h>

#define L 45
#define LP 48              // padded label count
#define SMAX 512
#define START_IDX 43
#define STOP_IDX 44
#define PF 4               // logit prefetch distance
#define LOG2E 1.4426950408889634f
#define LN2   0.6931471805599453f

__device__ __forceinline__ float ex2f(float x) {
    float r; asm("ex2.approx.ftz.f32 %0, %1;" : "=f"(r) : "f"(x)); return r;
}
__device__ __forceinline__ float lg2f(float x) {
    float r; asm("lg2.approx.ftz.f32 %0, %1;" : "=f"(r) : "f"(x)); return r;
}
__device__ __forceinline__ void fma2(unsigned long long& d,
                                     unsigned long long a, unsigned long long b) {
    asm("fma.rn.f32x2 %0, %1, %2, %0;" : "+l"(d) : "l"(a), "l"(b));
}
__device__ __forceinline__ void add2(unsigned long long& d, unsigned long long a) {
    asm("add.rn.f32x2 %0, %0, %1;" : "+l"(d) : "l"(a));
}
__device__ __forceinline__ unsigned long long pack2(float lo, float hi) {
    unsigned long long v;
    asm("mov.b64 %0, {%1, %2};" : "=l"(v) : "f"(lo), "f"(hi)); return v;
}
__device__ __forceinline__ float2 unpack2(unsigned long long v) {
    float2 f; asm("mov.b64 {%0, %1}, %2;" : "=f"(f.x), "=f"(f.y) : "l"(v)); return f;
}

// 256-thread block = 4 independent batch-pairs. Pair p (batch) = warps 2p,2p+1
// -> the 8 warps cover all four SMSPs evenly (wid%4). Within a pair, thread
// i = tid&63: i<45 are e-producers (one label row each, expT row in regs,
// packed f32x2 dot), i==45 is the dedicated scale-increment producer (owns a
// copy of row 0; its lg2 runs in parallel with everyone's ex2).
// Pairs sync via named barrier (id = pair+1, 64 threads) -- batches with
// different lens never couple.
// Recurrence (base-2, scaled-linear): s_i = sum_j expT[i,j]*e[j];
//   e'_i = s_i * 2^(lgt2_i - c2);  M2 += c2;  c2' = lg2(s_0)+lgt2_0-c2 (stale).
__global__ __launch_bounds__(256) void crf_fwd_kernel(
    const float* __restrict__ logits,      // [B, S, L]
    const int*   __restrict__ lens,        // [B]
    const float* __restrict__ trans,       // [L, L], trans[i*L+j]=score(j->i)
    float*       __restrict__ out)         // [B]
{
    const int pair = threadIdx.x >> 6;     // 0..3 (which batch in block)
    const int i    = threadIdx.x & 63;     // thread within pair
    const int b    = blockIdx.x * 4 + pair;
    const int bar  = pair + 1;             // named barrier id

    __shared__ __align__(16) float e_sm[4][2][LP];
    __shared__ float c_sm[4][2];
    __shared__ float m_sm[4];
    __shared__ float red_sm[4][64];

    float (*e_s)[LP] = e_sm[pair];
    float* c_s = c_sm[pair];
    float* red = red_sm[pair];

    const bool is_e = (i < L);
    const bool is_c = (i == L);            // thread 45 of the pair
    const bool ld   = is_e | is_c;
    const int  lab  = is_e ? i : 0;

    if (i < LP) { e_s[0][i] = 0.f; e_s[1][i] = 0.f; }
    if (i == 0) { c_s[0] = 0.f; c_s[1] = 0.f; }

    // packed expT row in registers
    unsigned long long rowp[LP / 2];
#pragma unroll
    for (int m = 0; m < LP / 2; m++) rowp[m] = 0ull;
    if (ld) {
#pragma unroll
        for (int m = 0; m < LP / 2; m++) {
            const float x0 = __expf(trans[lab * L + 2 * m]);
            const float x1 = (2 * m + 1 < L) ? __expf(trans[lab * L + 2 * m + 1]) : 0.f;
            rowp[m] = pack2(x0, x1);
        }
    }

    const int len = lens[b];
    const float* lg = logits + (size_t)b * SMAX * L;

    // ---- t = 0 analytically: alpha0 = logit[0] + T[:, START] ----
    float a0v = 0.f;
    if (is_e) a0v = lg[i] + trans[i * L + START_IDX];
    if (i == 0) m_sm[pair] = a0v;
    asm volatile("bar.sync %0, 64;" :: "r"(bar) : "memory");
    const float mu0 = m_sm[pair];
    float M2 = mu0 * LOG2E;                // running scale (base-2)
    float e_loc = ex2f((a0v - mu0) * LOG2E);
    if (is_e) e_s[1][i] = e_loc;

    // ---- prefetch logits (pre-scaled by log2e) ----
    float lgbuf[PF];
#pragma unroll
    for (int u = 0; u < PF; u++) {
        const int t = 1 + u;
        lgbuf[u] = (ld && t < len) ? lg[t * L + lab] * LOG2E : 0.f;
    }

#define STEP(tt, uu) do {                                                     \
        const int p_ = (tt) & 1;                                              \
        asm volatile("bar.sync %0, 64;" :: "r"(bar) : "memory");              \
        const float lgt2_ = lgbuf[uu];                                        \
        { const int tn_ = (tt) + PF;                                          \
          lgbuf[uu] = (ld && tn_ < len) ? lg[tn_ * L + lab] * LOG2E : 0.f; }  \
        const float c2_ = c_s[p_ ^ 1];                                        \
        const ulonglong2* e2_ = (const ulonglong2*)(e_s[p_]);                 \
        unsigned long long ac_[8] = {0,0,0,0,0,0,0,0};                        \
        _Pragma("unroll")                                                     \
        for (int h_ = 0; h_ < LP / 4; h_++) {                                 \
            const ulonglong2 w_ = e2_[h_];                                    \
            fma2(ac_[(2 * h_)     & 7], rowp[2 * h_],     w_.x);              \
            fma2(ac_[(2 * h_ + 1) & 7], rowp[2 * h_ + 1], w_.y);              \
        }                                                                     \
        add2(ac_[0], ac_[4]); add2(ac_[1], ac_[5]);                           \
        add2(ac_[2], ac_[6]); add2(ac_[3], ac_[7]);                           \
        add2(ac_[0], ac_[2]); add2(ac_[1], ac_[3]);                           \
        add2(ac_[0], ac_[1]);                                                 \
        const float2 f_ = unpack2(ac_[0]);                                    \
        const float s_ = f_.x + f_.y;                                         \
        if (is_e) {                                                           \
            const float en_ = s_ * ex2f(lgt2_ - c2_);                         \
            e_s[p_ ^ 1][i] = en_; e_loc = en_;                                \
        }                                                                     \
        if (is_c) c_s[p_] = lg2f(s_) + lgt2_ - c2_;                           \
        M2 += c2_;                                                            \
    } while (0)

    // main loop: full PF-chunks, branch-free bodies (prefetch is predicated)
    int t = 1;
    for (; t + PF <= len; t += PF) {
        STEP(t + 0, 0);
        STEP(t + 1, 1);
        STEP(t + 2, 2);
        STEP(t + 3, 3);
    }
    // tail (<= 3 steps), constant lgbuf indices
    if (t < len) { STEP(t, 0); t++; }
    if (t < len) { STEP(t, 1); t++; }
    if (t < len) { STEP(t, 2); }
#undef STEP

    // ---- epilogue: out[b] = LSE_i( alpha_i + T[STOP, i] ) ----
    red[i] = is_e ? ((M2 + lg2f(e_loc)) * LN2 + trans[STOP_IDX * L + i]) : -1e30f;
    asm volatile("bar.sync %0, 64;" :: "r"(bar) : "memory");
    if (i == 0) {
        float m = red[0];
#pragma unroll
        for (int j = 1; j < L; j++) m = fmaxf(m, red[j]);
        float s = 0.f;
#pragma unroll
        for (int j = 0; j < L; j++) s += __expf(red[j] - m);
        out[b] = m + __logf(s);
    }
}

extern "C" void kernel_launch(void* const* d_in, const int* in_sizes, int n_in,
                              void* d_out, int out_size) {
    const float* logits = (const float*)d_in[0];   // [1024, 512, 45] f32
    const int*   lens   = (const int*)d_in[1];     // [1024] i32
    const float* trans  = (const float*)d_in[2];   // [45, 45] f32
    float* out = (float*)d_out;                    // [1024] f32

    const int B = in_sizes[1];                     // 1024
    crf_fwd_kernel<<<B / 4, 256>>>(logits, lens, trans, out);
}